// round 12
// baseline (speedup 1.0000x reference)
#include <cuda_runtime.h>
#include <cuda_bf16.h>
#include <cstdint>

#define DD       128
#define NT       256
#define TILE_M   128
#define WSROW    136                      // padded bf16 row stride (272 B)
#define N_MESH_C 40962
#define N_GRID_C 200000
#define N_EDGE_C 600000

// shared memory map (byte offsets). A/W tiles are 128 x 136 bf16 = 34816 B.
#define SM_AHI   0
#define SM_ALO   34816
#define SM_WHI   69632
#define SM_WLO   104448
#define SM_IDX   139264
#define SM_TOTAL (SM_IDX + 2 * TILE_M * 4)

#define WIMG_ELEMS (2 * TILE_M * WSROW)   // hi plane + lo plane per weight

// -------------------- global scratch (allocation-free) ----------------------
__device__ __nv_bfloat16 g_Wimg[7 * WIMG_ELEMS];
__device__ __align__(16) float g_Pmesh[(size_t)N_MESH_C * DD];
__device__ __align__(16) float g_Pgrid[(size_t)N_GRID_C * DD];
__device__ __align__(16) float g_efeat[(size_t)N_EDGE_C * DD];

// -------------------- helpers ----------------------------------------------
__device__ __forceinline__ float4 ld4(const float* p) { return *reinterpret_cast<const float4*>(p); }
__device__ __forceinline__ float2 ld2(const float* p) { return *reinterpret_cast<const float2*>(p); }
__device__ __forceinline__ float silu_f(float x) { return x / (1.0f + __expf(-x)); }
__device__ __forceinline__ float qsum(float v) {
    v += __shfl_xor_sync(0xffffffffu, v, 1);
    v += __shfl_xor_sync(0xffffffffu, v, 2);
    return v;
}
__device__ __forceinline__ uint32_t s2u(const void* p) {
    uint32_t a;
    asm("{ .reg .u64 t; cvta.to.shared.u64 t, %1; cvt.u32.u64 %0, t; }" : "=r"(a) : "l"(p));
    return a;
}
__device__ __forceinline__ uint32_t packbf2(float x, float y) {
    __nv_bfloat162 t = __floats2bfloat162_rn(x, y);
    return *reinterpret_cast<uint32_t*>(&t);
}
// split-bf16 store of 2 consecutive k values at (r, k) into hi/lo tiles
__device__ __forceinline__ void conv_store2(char* Thi, char* Tlo, int r, int k, float x, float y) {
    __nv_bfloat16 hx = __float2bfloat16(x), hy = __float2bfloat16(y);
    float rx = x - __bfloat162float(hx), ry = y - __bfloat162float(hy);
    uint32_t off = (uint32_t)r * (WSROW * 2) + (uint32_t)k * 2;
    *reinterpret_cast<uint32_t*>(Thi + off) = packbf2(__bfloat162float(hx), __bfloat162float(hy));
    *reinterpret_cast<uint32_t*>(Tlo + off) = packbf2(rx, ry);
}

// Stage a TILE_M x 128 float tile (zero-padded) into split-bf16 smem tiles.
__device__ __forceinline__ void stage_A(char* Ahi, char* Alo, const float* gsrc,
                                        int row0, int rows_valid) {
    for (int idx = threadIdx.x; idx < TILE_M * 32; idx += NT) {
        int r = idx >> 5, c4 = (idx & 31) * 4;
        float4 v = make_float4(0.f, 0.f, 0.f, 0.f);
        if (r < rows_valid) v = ld4(gsrc + (size_t)(row0 + r) * DD + c4);
        conv_store2(Ahi, Alo, r, c4,     v.x, v.y);
        conv_store2(Ahi, Alo, r, c4 + 2, v.z, v.w);
    }
}

// Copy one weight image (hi+lo planes, contiguous 69632 B) into smem WHI/WLO.
__device__ __forceinline__ void copy_wimg(char* smbase, int widx) {
    const uint4* s = reinterpret_cast<const uint4*>(g_Wimg + (size_t)widx * WIMG_ELEMS);
    uint4* d = reinterpret_cast<uint4*>(smbase + SM_WHI);
    for (int i = threadIdx.x; i < 4352; i += NT) d[i] = s[i];
}

// -------------------- mma.sync core -----------------------------------------
// One split pass: acc[nf][0..3] += A(16 rows) @ W (K=128), bf16 operands.
__device__ __forceinline__ void gemm_pass(uint32_t aBase, uint32_t wBase, float acc[16][4]) {
    #pragma unroll 2
    for (int ks = 0; ks < 8; ks++) {
        uint32_t a0, a1, a2, a3;
        asm volatile("ldmatrix.sync.aligned.m8n8.x4.shared.b16 {%0,%1,%2,%3}, [%4];"
                     : "=r"(a0), "=r"(a1), "=r"(a2), "=r"(a3)
                     : "r"(aBase + ks * 32));
        #pragma unroll
        for (int p = 0; p < 8; p++) {
            uint32_t b0, b1, b2, b3;
            asm volatile("ldmatrix.sync.aligned.m8n8.x4.shared.b16 {%0,%1,%2,%3}, [%4];"
                         : "=r"(b0), "=r"(b1), "=r"(b2), "=r"(b3)
                         : "r"(wBase + p * (16 * WSROW * 2) + ks * 32));
            asm volatile("mma.sync.aligned.m16n8k16.row.col.f32.bf16.bf16.f32 "
                         "{%0,%1,%2,%3}, {%4,%5,%6,%7}, {%8,%9}, {%0,%1,%2,%3};"
                         : "+f"(acc[2*p][0]), "+f"(acc[2*p][1]), "+f"(acc[2*p][2]), "+f"(acc[2*p][3])
                         : "r"(a0), "r"(a1), "r"(a2), "r"(a3), "r"(b0), "r"(b1));
            asm volatile("mma.sync.aligned.m16n8k16.row.col.f32.bf16.bf16.f32 "
                         "{%0,%1,%2,%3}, {%4,%5,%6,%7}, {%8,%9}, {%0,%1,%2,%3};"
                         : "+f"(acc[2*p+1][0]), "+f"(acc[2*p+1][1]), "+f"(acc[2*p+1][2]), "+f"(acc[2*p+1][3])
                         : "r"(a0), "r"(a1), "r"(a2), "r"(a3), "r"(b2), "r"(b3));
        }
    }
}

// 3-pass split accumulation: AhWh + AhWl + AlWh.
__device__ __forceinline__ void gemm3(uint32_t smem, int wid, int lane, float acc[16][4]) {
    uint32_t aoff = (uint32_t)(lane & 15) * (WSROW * 2) + (uint32_t)(lane >> 4) * 16;
    uint32_t boff = ((uint32_t)((lane & 7) + ((lane >> 4) << 3))) * (WSROW * 2)
                  + (uint32_t)((lane >> 3) & 1) * 16;
    uint32_t AHb = smem + SM_AHI + (uint32_t)wid * 16 * (WSROW * 2) + aoff;
    uint32_t ALb = smem + SM_ALO + (uint32_t)wid * 16 * (WSROW * 2) + aoff;
    uint32_t WHb = smem + SM_WHI + boff;
    uint32_t WLb = smem + SM_WLO + boff;
    #pragma unroll 1
    for (int p3 = 0; p3 < 3; p3++) {
        uint32_t ab = (p3 == 2) ? ALb : AHb;
        uint32_t wb = (p3 == 1) ? WLb : WHb;
        gemm_pass(ab, wb, acc);
    }
}

__device__ __forceinline__ void zero_acc(float acc[16][4]) {
    #pragma unroll
    for (int i = 0; i < 16; i++) {
        acc[i][0] = 0.f; acc[i][1] = 0.f; acc[i][2] = 0.f; acc[i][3] = 0.f;
    }
}

// -------------------- weight pre-conversion ---------------------------------
// images store WT[n][k] = W[k][n] split into bf16 hi/lo planes, rows padded to 136.
// blockIdx: 0:Ws 1:Wd 2:We 3:W1e 4:Wn0[0:128) 5:Wn0[128:256) 6:Wn1
__global__ void convw_kernel(const float* __restrict__ Ws, const float* __restrict__ Wd,
                             const float* __restrict__ We, const float* __restrict__ W1e,
                             const float* __restrict__ Wn0, const float* __restrict__ Wn1) {
    int b = blockIdx.x;
    const float* src; int roff = 0;
    switch (b) {
        case 0: src = Ws;  break;
        case 1: src = Wd;  break;
        case 2: src = We;  break;
        case 3: src = W1e; break;
        case 4: src = Wn0; break;
        case 5: src = Wn0; roff = 128; break;
        default: src = Wn1; break;
    }
    __nv_bfloat16* hi = g_Wimg + (size_t)b * WIMG_ELEMS;
    __nv_bfloat16* lo = hi + TILE_M * WSROW;
    for (int idx = threadIdx.x; idx < DD * DD; idx += NT) {
        int n = idx >> 7, k = idx & 127;
        float x = src[(size_t)(roff + k) * DD + n];
        __nv_bfloat16 h = __float2bfloat16(x);
        hi[n * WSROW + k] = h;
        lo[n * WSROW + k] = __float2bfloat16(x - __bfloat162float(h));
    }
}

// -------------------- proj: C = A @ W ---------------------------------------
__global__ void __launch_bounds__(NT)
proj_mm(const float* __restrict__ A, int widx, float* __restrict__ C, int M) {
    extern __shared__ char sm[];
    uint32_t smem = s2u(sm);
    int tid = threadIdx.x, wid = tid >> 5, lane = tid & 31;
    int gid = lane >> 2, tg = lane & 3;
    int m0 = blockIdx.x * TILE_M;
    int rv = M - m0; if (rv > TILE_M) rv = TILE_M;

    stage_A(sm + SM_AHI, sm + SM_ALO, A, m0, rv);
    copy_wimg(sm, widx);
    __syncthreads();

    float acc[16][4];
    zero_acc(acc);
    gemm3(smem, wid, lane, acc);

    int r0 = m0 + wid * 16 + gid, r1 = r0 + 8;
    #pragma unroll
    for (int nf = 0; nf < 16; nf++) {
        int col = nf * 8 + tg * 2;
        if (r0 < M) *reinterpret_cast<float2*>(C + (size_t)r0 * DD + col) = make_float2(acc[nf][0], acc[nf][1]);
        if (r1 < M) *reinterpret_cast<float2*>(C + (size_t)r1 * DD + col) = make_float2(acc[nf][2], acc[nf][3]);
    }
}

// -------------------- edge kernel -------------------------------------------
__global__ void __launch_bounds__(NT)
edge_mm(const float* __restrict__ m2g, const int* __restrict__ src, const int* __restrict__ dst,
        const float* __restrict__ b0, const float* __restrict__ b1e,
        const float* __restrict__ ge, const float* __restrict__ be) {
    extern __shared__ char sm[];
    uint32_t smem = s2u(sm);
    char* Ahi = sm + SM_AHI; char* Alo = sm + SM_ALO;
    int tid = threadIdx.x, wid = tid >> 5, lane = tid & 31;
    int gid = lane >> 2, tg = lane & 3;
    int e0 = blockIdx.x * TILE_M;
    int rv = N_EDGE_C - e0; if (rv > TILE_M) rv = TILE_M;

    stage_A(Ahi, Alo, m2g, e0, rv);
    copy_wimg(sm, 2);                       // We
    __syncthreads();

    float acc[16][4];
    zero_acc(acc);
    gemm3(smem, wid, lane, acc);            // m2g @ We

    // epilogue 1: + Pmesh[src] + Pgrid[dst] + b0, silu -> h into A tiles (own rows)
    int r0l = wid * 16 + gid, r1l = r0l + 8;
    int er0 = e0 + r0l, er1 = e0 + r1l;
    bool v0 = er0 < N_EDGE_C, v1 = er1 < N_EDGE_C;
    int s0 = 0, d0 = 0, s1 = 0, d1 = 0;
    if (v0) { s0 = __ldg(src + er0); d0 = __ldg(dst + er0); }
    if (v1) { s1 = __ldg(src + er1); d1 = __ldg(dst + er1); }
    #pragma unroll
    for (int nf = 0; nf < 16; nf++) {
        int col = nf * 8 + tg * 2;
        float2 bb = ld2(b0 + col);
        float x0 = acc[nf][0] + bb.x, y0 = acc[nf][1] + bb.y;
        float x1 = acc[nf][2] + bb.x, y1 = acc[nf][3] + bb.y;
        if (v0) {
            float2 pm = ld2(g_Pmesh + (size_t)s0 * DD + col);
            float2 pg = ld2(g_Pgrid + (size_t)d0 * DD + col);
            x0 += pm.x + pg.x; y0 += pm.y + pg.y;
        }
        if (v1) {
            float2 pm = ld2(g_Pmesh + (size_t)s1 * DD + col);
            float2 pg = ld2(g_Pgrid + (size_t)d1 * DD + col);
            x1 += pm.x + pg.x; y1 += pm.y + pg.y;
        }
        conv_store2(Ahi, Alo, r0l, col, silu_f(x0), silu_f(y0));
        conv_store2(Ahi, Alo, r1l, col, silu_f(x1), silu_f(y1));
    }
    __syncthreads();                        // all warps done with W (We)
    copy_wimg(sm, 3);                       // W1e
    __syncthreads();

    zero_acc(acc);
    gemm3(smem, wid, lane, acc);            // h @ W1e

    // epilogue 2: +b1e, LayerNorm (warp owns full rows -> quad shuffles), store
    float s1a = 0.f, s2a = 0.f, s1b = 0.f, s2b = 0.f;
    #pragma unroll
    for (int nf = 0; nf < 16; nf++) {
        int col = nf * 8 + tg * 2;
        float2 bb = ld2(b1e + col);
        acc[nf][0] += bb.x; acc[nf][1] += bb.y;
        acc[nf][2] += bb.x; acc[nf][3] += bb.y;
        s1a += acc[nf][0] + acc[nf][1];
        s2a += acc[nf][0]*acc[nf][0] + acc[nf][1]*acc[nf][1];
        s1b += acc[nf][2] + acc[nf][3];
        s2b += acc[nf][2]*acc[nf][2] + acc[nf][3]*acc[nf][3];
    }
    s1a = qsum(s1a); s2a = qsum(s2a); s1b = qsum(s1b); s2b = qsum(s2b);
    float mu0 = s1a * 0.0078125f, rstd0 = rsqrtf(s2a * 0.0078125f - mu0*mu0 + 1e-5f);
    float mu1 = s1b * 0.0078125f, rstd1 = rsqrtf(s2b * 0.0078125f - mu1*mu1 + 1e-5f);
    #pragma unroll
    for (int nf = 0; nf < 16; nf++) {
        int col = nf * 8 + tg * 2;
        float2 gv = ld2(ge + col), bv = ld2(be + col);
        if (v0)
            *reinterpret_cast<float2*>(g_efeat + (size_t)er0 * DD + col) =
                make_float2((acc[nf][0]-mu0)*rstd0*gv.x + bv.x, (acc[nf][1]-mu0)*rstd0*gv.y + bv.y);
        if (v1)
            *reinterpret_cast<float2*>(g_efeat + (size_t)er1 * DD + col) =
                make_float2((acc[nf][2]-mu1)*rstd1*gv.x + bv.x, (acc[nf][3]-mu1)*rstd1*gv.y + bv.y);
    }
}

// -------------------- node kernel -------------------------------------------
__global__ void __launch_bounds__(NT)
node_mm(const float* __restrict__ grid, const int* __restrict__ dst,
        const float* __restrict__ bn0, const float* __restrict__ bn1,
        const float* __restrict__ gn, const float* __restrict__ bnv,
        float* __restrict__ out) {
    extern __shared__ char sm[];
    uint32_t smem = s2u(sm);
    char* Ahi = sm + SM_AHI; char* Alo = sm + SM_ALO;
    int* sLo = (int*)(sm + SM_IDX);
    int* sHi = sLo + TILE_M;
    int tid = threadIdx.x, wid = tid >> 5, lane = tid & 31;
    int gid = lane >> 2, tg = lane & 3;
    int n0 = blockIdx.x * TILE_M;
    int rv = N_GRID_C - n0; if (rv > TILE_M) rv = TILE_M;

    // per-node edge ranges (dst sorted)
    if (tid < TILE_M) {
        int n = n0 + tid;
        int lo = 0, hi = N_EDGE_C;
        while (lo < hi) { int m = (lo + hi) >> 1; if (__ldg(dst + m) <  n) lo = m + 1; else hi = m; }
        sLo[tid] = lo;
        int lo2 = lo, hi2 = N_EDGE_C;
        while (lo2 < hi2) { int m = (lo2 + hi2) >> 1; if (__ldg(dst + m) <= n) lo2 = m + 1; else hi2 = m; }
        sHi[tid] = lo2;
    }
    __syncthreads();

    // segment-sum into A tiles (warp w owns rows [16w,16w+16), lane covers 4 cols)
    {
        int c4 = lane * 4;
        #pragma unroll
        for (int i = 0; i < 16; i++) {
            int r = wid * 16 + i;
            int lo = sLo[r], hi = sHi[r];
            float4 s = make_float4(0.f, 0.f, 0.f, 0.f);
            for (int e = lo; e < hi; e++) {
                float4 v = ld4(g_efeat + (size_t)e * DD + c4);
                s.x += v.x; s.y += v.y; s.z += v.z; s.w += v.w;
            }
            conv_store2(Ahi, Alo, r, c4,     s.x, s.y);
            conv_store2(Ahi, Alo, r, c4 + 2, s.z, s.w);
        }
    }
    copy_wimg(sm, 5);                       // Wn0 rows [128:256)
    __syncthreads();

    float acc[16][4];
    zero_acc(acc);
    gemm3(smem, wid, lane, acc);            // agg @ Wn0_hi-half
    __syncthreads();

    stage_A(Ahi, Alo, grid, n0, rv);
    copy_wimg(sm, 4);                       // Wn0 rows [0:128)
    __syncthreads();
    gemm3(smem, wid, lane, acc);            // += grid @ Wn0_lo-half

    // silu(+bn0) -> h into A tiles (own rows)
    int r0l = wid * 16 + gid, r1l = r0l + 8;
    #pragma unroll
    for (int nf = 0; nf < 16; nf++) {
        int col = nf * 8 + tg * 2;
        float2 bb = ld2(bn0 + col);
        conv_store2(Ahi, Alo, r0l, col, silu_f(acc[nf][0] + bb.x), silu_f(acc[nf][1] + bb.y));
        conv_store2(Ahi, Alo, r1l, col, silu_f(acc[nf][2] + bb.x), silu_f(acc[nf][3] + bb.y));
    }
    __syncthreads();
    copy_wimg(sm, 6);                       // Wn1
    __syncthreads();

    zero_acc(acc);
    gemm3(smem, wid, lane, acc);            // h @ Wn1

    // +bn1, LayerNorm, +grid residual, store
    int r0 = n0 + r0l, r1 = n0 + r1l;
    bool v0 = r0 < N_GRID_C, v1 = r1 < N_GRID_C;
    float s1a = 0.f, s2a = 0.f, s1b = 0.f, s2b = 0.f;
    #pragma unroll
    for (int nf = 0; nf < 16; nf++) {
        int col = nf * 8 + tg * 2;
        float2 bb = ld2(bn1 + col);
        acc[nf][0] += bb.x; acc[nf][1] += bb.y;
        acc[nf][2] += bb.x; acc[nf][3] += bb.y;
        s1a += acc[nf][0] + acc[nf][1];
        s2a += acc[nf][0]*acc[nf][0] + acc[nf][1]*acc[nf][1];
        s1b += acc[nf][2] + acc[nf][3];
        s2b += acc[nf][2]*acc[nf][2] + acc[nf][3]*acc[nf][3];
    }
    s1a = qsum(s1a); s2a = qsum(s2a); s1b = qsum(s1b); s2b = qsum(s2b);
    float mu0 = s1a * 0.0078125f, rstd0 = rsqrtf(s2a * 0.0078125f - mu0*mu0 + 1e-5f);
    float mu1 = s1b * 0.0078125f, rstd1 = rsqrtf(s2b * 0.0078125f - mu1*mu1 + 1e-5f);
    #pragma unroll
    for (int nf = 0; nf < 16; nf++) {
        int col = nf * 8 + tg * 2;
        float2 gv = ld2(gn + col), bv = ld2(bnv + col);
        if (v0) {
            float2 gr = ld2(grid + (size_t)r0 * DD + col);
            *reinterpret_cast<float2*>(out + (size_t)r0 * DD + col) =
                make_float2((acc[nf][0]-mu0)*rstd0*gv.x + bv.x + gr.x,
                            (acc[nf][1]-mu0)*rstd0*gv.y + bv.y + gr.y);
        }
        if (v1) {
            float2 gr = ld2(grid + (size_t)r1 * DD + col);
            *reinterpret_cast<float2*>(out + (size_t)r1 * DD + col) =
                make_float2((acc[nf][2]-mu1)*rstd1*gv.x + bv.x + gr.x,
                            (acc[nf][3]-mu1)*rstd1*gv.y + bv.y + gr.y);
        }
    }
}

// -------------------- launch -------------------------------------------------
extern "C" void kernel_launch(void* const* d_in, const int* in_sizes, int n_in,
                              void* d_out, int out_size) {
    (void)in_sizes; (void)n_in; (void)out_size;

    const float* m2g  = (const float*)d_in[0];
    const float* grid = (const float*)d_in[1];
    const float* mesh = (const float*)d_in[2];
    const int*   src  = (const int*)  d_in[3];
    const int*   dst  = (const int*)  d_in[4];
    const float* We   = (const float*)d_in[5];
    const float* Ws   = (const float*)d_in[6];
    const float* Wd   = (const float*)d_in[7];
    const float* b0   = (const float*)d_in[8];
    const float* W1e  = (const float*)d_in[9];
    const float* b1e  = (const float*)d_in[10];
    const float* ge   = (const float*)d_in[11];
    const float* be   = (const float*)d_in[12];
    const float* Wn0  = (const float*)d_in[13];
    const float* bn0  = (const float*)d_in[14];
    const float* Wn1  = (const float*)d_in[15];
    const float* bn1  = (const float*)d_in[16];
    const float* gn   = (const float*)d_in[17];
    const float* bn   = (const float*)d_in[18];
    float* out = (float*)d_out;

    cudaFuncSetAttribute(proj_mm, cudaFuncAttributeMaxDynamicSharedMemorySize, SM_TOTAL);
    cudaFuncSetAttribute(edge_mm, cudaFuncAttributeMaxDynamicSharedMemorySize, SM_TOTAL);
    cudaFuncSetAttribute(node_mm, cudaFuncAttributeMaxDynamicSharedMemorySize, SM_TOTAL);

    void *pm = nullptr, *pg = nullptr;
    cudaGetSymbolAddress(&pm, g_Pmesh);
    cudaGetSymbolAddress(&pg, g_Pgrid);

    convw_kernel<<<7, NT>>>(Ws, Wd, We, W1e, Wn0, Wn1);

    int gb_mesh = (N_MESH_C + TILE_M - 1) / TILE_M;
    int gb_grid = (N_GRID_C + TILE_M - 1) / TILE_M;
    int gb_edge = (N_EDGE_C + TILE_M - 1) / TILE_M;

    proj_mm<<<gb_mesh, NT, SM_TOTAL>>>(mesh, 0, (float*)pm, N_MESH_C);
    proj_mm<<<gb_grid, NT, SM_TOTAL>>>(grid, 1, (float*)pg, N_GRID_C);
    edge_mm<<<gb_edge, NT, SM_TOTAL>>>(m2g, src, dst, b0, b1e, ge, be);
    node_mm<<<gb_grid, NT, SM_TOTAL>>>(grid, dst, bn0, bn1, gn, bn, out);
}

// round 13
// speedup vs baseline: 1.1856x; 1.1856x over previous
#include <cuda_runtime.h>
#include <cuda_bf16.h>
#include <cstdint>

#define DD       128
#define NT       128                      // 4 warps per CTA
#define TILE_M   64                       // rows per CTA tile
#define WSROW    136                      // padded bf16 row stride (272 B)
#define N_MESH_C 40962
#define N_GRID_C 200000
#define N_EDGE_C 600000

// shared memory map (byte offsets).
// A tiles: 64 x 136 bf16 = 17408 B.  W tiles: 128 x 136 bf16 = 34816 B.
#define SM_AHI   0
#define SM_ALO   17408
#define SM_WHI   34816
#define SM_WLO   69632
#define SM_IDX   104448
#define SM_TOTAL (SM_IDX + 2 * TILE_M * 4)   // 104960 B -> 2 CTAs/SM

#define WIMG_ELEMS (2 * DD * WSROW)       // hi plane + lo plane per weight (128 rows each)

// -------------------- global scratch (allocation-free) ----------------------
__device__ __nv_bfloat16 g_Wimg[7 * WIMG_ELEMS];
__device__ __align__(16) float g_Pmesh[(size_t)N_MESH_C * DD];
__device__ __align__(16) float g_Pgrid[(size_t)N_GRID_C * DD];
__device__ __align__(16) float g_efeat[(size_t)N_EDGE_C * DD];

// -------------------- helpers ----------------------------------------------
__device__ __forceinline__ float4 ld4(const float* p) { return *reinterpret_cast<const float4*>(p); }
__device__ __forceinline__ float2 ld2(const float* p) { return *reinterpret_cast<const float2*>(p); }
__device__ __forceinline__ float silu_f(float x) { return x / (1.0f + __expf(-x)); }
__device__ __forceinline__ float qsum(float v) {
    v += __shfl_xor_sync(0xffffffffu, v, 1);
    v += __shfl_xor_sync(0xffffffffu, v, 2);
    return v;
}
__device__ __forceinline__ uint32_t s2u(const void* p) {
    uint32_t a;
    asm("{ .reg .u64 t; cvta.to.shared.u64 t, %1; cvt.u32.u64 %0, t; }" : "=r"(a) : "l"(p));
    return a;
}
__device__ __forceinline__ uint32_t packbf2(float x, float y) {
    __nv_bfloat162 t = __floats2bfloat162_rn(x, y);
    return *reinterpret_cast<uint32_t*>(&t);
}
// split-bf16 store of 2 consecutive k values at (r, k) into hi/lo tiles
__device__ __forceinline__ void conv_store2(char* Thi, char* Tlo, int r, int k, float x, float y) {
    __nv_bfloat16 hx = __float2bfloat16(x), hy = __float2bfloat16(y);
    float rx = x - __bfloat162float(hx), ry = y - __bfloat162float(hy);
    uint32_t off = (uint32_t)r * (WSROW * 2) + (uint32_t)k * 2;
    *reinterpret_cast<uint32_t*>(Thi + off) = packbf2(__bfloat162float(hx), __bfloat162float(hy));
    *reinterpret_cast<uint32_t*>(Tlo + off) = packbf2(rx, ry);
}

// Stage a TILE_M x 128 float tile (zero-padded) into split-bf16 smem tiles.
__device__ __forceinline__ void stage_A(char* Ahi, char* Alo, const float* gsrc,
                                        int row0, int rows_valid) {
    for (int idx = threadIdx.x; idx < TILE_M * 32; idx += NT) {
        int r = idx >> 5, c4 = (idx & 31) * 4;
        float4 v = make_float4(0.f, 0.f, 0.f, 0.f);
        if (r < rows_valid) v = ld4(gsrc + (size_t)(row0 + r) * DD + c4);
        conv_store2(Ahi, Alo, r, c4,     v.x, v.y);
        conv_store2(Ahi, Alo, r, c4 + 2, v.z, v.w);
    }
}

// Copy one weight image (hi+lo planes, contiguous 69632 B) into smem WHI/WLO.
__device__ __forceinline__ void copy_wimg(char* smbase, int widx) {
    const uint4* s = reinterpret_cast<const uint4*>(g_Wimg + (size_t)widx * WIMG_ELEMS);
    uint4* d = reinterpret_cast<uint4*>(smbase + SM_WHI);
    for (int i = threadIdx.x; i < 4352; i += NT) d[i] = s[i];
}

// -------------------- mma.sync core -----------------------------------------
// One split pass: acc[nf][0..3] += A(16 rows) @ W (K=128), bf16 operands.
__device__ __forceinline__ void gemm_pass(uint32_t aBase, uint32_t wBase, float acc[16][4]) {
    #pragma unroll 2
    for (int ks = 0; ks < 8; ks++) {
        uint32_t a0, a1, a2, a3;
        asm volatile("ldmatrix.sync.aligned.m8n8.x4.shared.b16 {%0,%1,%2,%3}, [%4];"
                     : "=r"(a0), "=r"(a1), "=r"(a2), "=r"(a3)
                     : "r"(aBase + ks * 32));
        #pragma unroll
        for (int p = 0; p < 8; p++) {
            uint32_t b0, b1, b2, b3;
            asm volatile("ldmatrix.sync.aligned.m8n8.x4.shared.b16 {%0,%1,%2,%3}, [%4];"
                         : "=r"(b0), "=r"(b1), "=r"(b2), "=r"(b3)
                         : "r"(wBase + p * (16 * WSROW * 2) + ks * 32));
            asm volatile("mma.sync.aligned.m16n8k16.row.col.f32.bf16.bf16.f32 "
                         "{%0,%1,%2,%3}, {%4,%5,%6,%7}, {%8,%9}, {%0,%1,%2,%3};"
                         : "+f"(acc[2*p][0]), "+f"(acc[2*p][1]), "+f"(acc[2*p][2]), "+f"(acc[2*p][3])
                         : "r"(a0), "r"(a1), "r"(a2), "r"(a3), "r"(b0), "r"(b1));
            asm volatile("mma.sync.aligned.m16n8k16.row.col.f32.bf16.bf16.f32 "
                         "{%0,%1,%2,%3}, {%4,%5,%6,%7}, {%8,%9}, {%0,%1,%2,%3};"
                         : "+f"(acc[2*p+1][0]), "+f"(acc[2*p+1][1]), "+f"(acc[2*p+1][2]), "+f"(acc[2*p+1][3])
                         : "r"(a0), "r"(a1), "r"(a2), "r"(a3), "r"(b2), "r"(b3));
        }
    }
}

// 3-pass split accumulation: AhWh + AhWl + AlWh.
__device__ __forceinline__ void gemm3(uint32_t smem, int wid, int lane, float acc[16][4]) {
    uint32_t aoff = (uint32_t)(lane & 15) * (WSROW * 2) + (uint32_t)(lane >> 4) * 16;
    uint32_t boff = ((uint32_t)((lane & 7) + ((lane >> 4) << 3))) * (WSROW * 2)
                  + (uint32_t)((lane >> 3) & 1) * 16;
    uint32_t AHb = smem + SM_AHI + (uint32_t)wid * 16 * (WSROW * 2) + aoff;
    uint32_t ALb = smem + SM_ALO + (uint32_t)wid * 16 * (WSROW * 2) + aoff;
    uint32_t WHb = smem + SM_WHI + boff;
    uint32_t WLb = smem + SM_WLO + boff;
    #pragma unroll 1
    for (int p3 = 0; p3 < 3; p3++) {
        uint32_t ab = (p3 == 2) ? ALb : AHb;
        uint32_t wb = (p3 == 1) ? WLb : WHb;
        gemm_pass(ab, wb, acc);
    }
}

__device__ __forceinline__ void zero_acc(float acc[16][4]) {
    #pragma unroll
    for (int i = 0; i < 16; i++) {
        acc[i][0] = 0.f; acc[i][1] = 0.f; acc[i][2] = 0.f; acc[i][3] = 0.f;
    }
}

// -------------------- weight pre-conversion ---------------------------------
// images store WT[n][k] = W[k][n] split into bf16 hi/lo planes, rows padded to 136.
// blockIdx: 0:Ws 1:Wd 2:We 3:W1e 4:Wn0[0:128) 5:Wn0[128:256) 6:Wn1
__global__ void convw_kernel(const float* __restrict__ Ws, const float* __restrict__ Wd,
                             const float* __restrict__ We, const float* __restrict__ W1e,
                             const float* __restrict__ Wn0, const float* __restrict__ Wn1) {
    int b = blockIdx.x;
    const float* src; int roff = 0;
    switch (b) {
        case 0: src = Ws;  break;
        case 1: src = Wd;  break;
        case 2: src = We;  break;
        case 3: src = W1e; break;
        case 4: src = Wn0; break;
        case 5: src = Wn0; roff = 128; break;
        default: src = Wn1; break;
    }
    __nv_bfloat16* hi = g_Wimg + (size_t)b * WIMG_ELEMS;
    __nv_bfloat16* lo = hi + DD * WSROW;
    for (int idx = threadIdx.x; idx < DD * DD; idx += 256) {
        int n = idx >> 7, k = idx & 127;
        float x = src[(size_t)(roff + k) * DD + n];
        __nv_bfloat16 h = __float2bfloat16(x);
        hi[n * WSROW + k] = h;
        lo[n * WSROW + k] = __float2bfloat16(x - __bfloat162float(h));
    }
}

// -------------------- proj: C = A @ W ---------------------------------------
__global__ void __launch_bounds__(NT, 2)
proj_mm(const float* __restrict__ A, int widx, float* __restrict__ C, int M) {
    extern __shared__ char sm[];
    uint32_t smem = s2u(sm);
    int tid = threadIdx.x, wid = tid >> 5, lane = tid & 31;
    int gid = lane >> 2, tg = lane & 3;
    int m0 = blockIdx.x * TILE_M;
    int rv = M - m0; if (rv > TILE_M) rv = TILE_M;

    stage_A(sm + SM_AHI, sm + SM_ALO, A, m0, rv);
    copy_wimg(sm, widx);
    __syncthreads();

    float acc[16][4];
    zero_acc(acc);
    gemm3(smem, wid, lane, acc);

    int r0 = m0 + wid * 16 + gid, r1 = r0 + 8;
    #pragma unroll
    for (int nf = 0; nf < 16; nf++) {
        int col = nf * 8 + tg * 2;
        if (r0 < M) *reinterpret_cast<float2*>(C + (size_t)r0 * DD + col) = make_float2(acc[nf][0], acc[nf][1]);
        if (r1 < M) *reinterpret_cast<float2*>(C + (size_t)r1 * DD + col) = make_float2(acc[nf][2], acc[nf][3]);
    }
}

// -------------------- edge kernel -------------------------------------------
__global__ void __launch_bounds__(NT, 2)
edge_mm(const float* __restrict__ m2g, const int* __restrict__ src, const int* __restrict__ dst,
        const float* __restrict__ b0, const float* __restrict__ b1e,
        const float* __restrict__ ge, const float* __restrict__ be) {
    extern __shared__ char sm[];
    uint32_t smem = s2u(sm);
    char* Ahi = sm + SM_AHI; char* Alo = sm + SM_ALO;
    int tid = threadIdx.x, wid = tid >> 5, lane = tid & 31;
    int gid = lane >> 2, tg = lane & 3;
    int e0 = blockIdx.x * TILE_M;
    int rv = N_EDGE_C - e0; if (rv > TILE_M) rv = TILE_M;

    stage_A(Ahi, Alo, m2g, e0, rv);
    copy_wimg(sm, 2);                       // We
    __syncthreads();

    // Pre-init accumulators with Pmesh[src] + Pgrid[dst] + b0.
    // These scattered LDGs (the longest-latency loads in the kernel) issue
    // here and overlap the entire LDSM/HMMA chain below.
    int r0l = wid * 16 + gid, r1l = r0l + 8;
    int er0 = e0 + r0l, er1 = e0 + r1l;
    bool v0 = er0 < N_EDGE_C, v1 = er1 < N_EDGE_C;
    int s0 = 0, d0 = 0, s1 = 0, d1 = 0;
    if (v0) { s0 = __ldg(src + er0); d0 = __ldg(dst + er0); }
    if (v1) { s1 = __ldg(src + er1); d1 = __ldg(dst + er1); }

    float acc[16][4];
    #pragma unroll
    for (int nf = 0; nf < 16; nf++) {
        int col = nf * 8 + tg * 2;
        float2 bb = ld2(b0 + col);
        float x0 = bb.x, y0 = bb.y, x1 = bb.x, y1 = bb.y;
        if (v0) {
            float2 pm = ld2(g_Pmesh + (size_t)s0 * DD + col);
            float2 pg = ld2(g_Pgrid + (size_t)d0 * DD + col);
            x0 += pm.x + pg.x; y0 += pm.y + pg.y;
        }
        if (v1) {
            float2 pm = ld2(g_Pmesh + (size_t)s1 * DD + col);
            float2 pg = ld2(g_Pgrid + (size_t)d1 * DD + col);
            x1 += pm.x + pg.x; y1 += pm.y + pg.y;
        }
        acc[nf][0] = x0; acc[nf][1] = y0; acc[nf][2] = x1; acc[nf][3] = y1;
    }

    gemm3(smem, wid, lane, acc);            // += m2g @ We

    // epilogue 1: silu -> h into A tiles (warp owns its rows)
    #pragma unroll
    for (int nf = 0; nf < 16; nf++) {
        int col = nf * 8 + tg * 2;
        conv_store2(Ahi, Alo, r0l, col, silu_f(acc[nf][0]), silu_f(acc[nf][1]));
        conv_store2(Ahi, Alo, r1l, col, silu_f(acc[nf][2]), silu_f(acc[nf][3]));
    }
    __syncthreads();                        // all warps done with We
    copy_wimg(sm, 3);                       // W1e
    __syncthreads();

    zero_acc(acc);
    gemm3(smem, wid, lane, acc);            // h @ W1e

    // epilogue 2: +b1e, LayerNorm (warp owns full rows -> quad shuffles), store
    float s1a = 0.f, s2a = 0.f, s1b = 0.f, s2b = 0.f;
    #pragma unroll
    for (int nf = 0; nf < 16; nf++) {
        int col = nf * 8 + tg * 2;
        float2 bb = ld2(b1e + col);
        acc[nf][0] += bb.x; acc[nf][1] += bb.y;
        acc[nf][2] += bb.x; acc[nf][3] += bb.y;
        s1a += acc[nf][0] + acc[nf][1];
        s2a += acc[nf][0]*acc[nf][0] + acc[nf][1]*acc[nf][1];
        s1b += acc[nf][2] + acc[nf][3];
        s2b += acc[nf][2]*acc[nf][2] + acc[nf][3]*acc[nf][3];
    }
    s1a = qsum(s1a); s2a = qsum(s2a); s1b = qsum(s1b); s2b = qsum(s2b);
    float mu0 = s1a * 0.0078125f, rstd0 = rsqrtf(s2a * 0.0078125f - mu0*mu0 + 1e-5f);
    float mu1 = s1b * 0.0078125f, rstd1 = rsqrtf(s2b * 0.0078125f - mu1*mu1 + 1e-5f);
    #pragma unroll
    for (int nf = 0; nf < 16; nf++) {
        int col = nf * 8 + tg * 2;
        float2 gv = ld2(ge + col), bv = ld2(be + col);
        if (v0)
            *reinterpret_cast<float2*>(g_efeat + (size_t)er0 * DD + col) =
                make_float2((acc[nf][0]-mu0)*rstd0*gv.x + bv.x, (acc[nf][1]-mu0)*rstd0*gv.y + bv.y);
        if (v1)
            *reinterpret_cast<float2*>(g_efeat + (size_t)er1 * DD + col) =
                make_float2((acc[nf][2]-mu1)*rstd1*gv.x + bv.x, (acc[nf][3]-mu1)*rstd1*gv.y + bv.y);
    }
}

// -------------------- node kernel -------------------------------------------
__global__ void __launch_bounds__(NT, 2)
node_mm(const float* __restrict__ grid, const int* __restrict__ dst,
        const float* __restrict__ bn0, const float* __restrict__ bn1,
        const float* __restrict__ gn, const float* __restrict__ bnv,
        float* __restrict__ out) {
    extern __shared__ char sm[];
    uint32_t smem = s2u(sm);
    char* Ahi = sm + SM_AHI; char* Alo = sm + SM_ALO;
    int* sLo = (int*)(sm + SM_IDX);
    int* sHi = sLo + TILE_M;
    int tid = threadIdx.x, wid = tid >> 5, lane = tid & 31;
    int gid = lane >> 2, tg = lane & 3;
    int n0 = blockIdx.x * TILE_M;
    int rv = N_GRID_C - n0; if (rv > TILE_M) rv = TILE_M;

    // per-node edge ranges (dst sorted)
    if (tid < TILE_M) {
        int n = n0 + tid;
        int lo = 0, hi = N_EDGE_C;
        while (lo < hi) { int m = (lo + hi) >> 1; if (__ldg(dst + m) <  n) lo = m + 1; else hi = m; }
        sLo[tid] = lo;
        int lo2 = lo, hi2 = N_EDGE_C;
        while (lo2 < hi2) { int m = (lo2 + hi2) >> 1; if (__ldg(dst + m) <= n) lo2 = m + 1; else hi2 = m; }
        sHi[tid] = lo2;
    }
    __syncthreads();

    // segment-sum into A tiles (warp w owns rows [16w,16w+16), lane covers 4 cols)
    {
        int c4 = lane * 4;
        #pragma unroll
        for (int i = 0; i < 16; i++) {
            int r = wid * 16 + i;
            int lo = sLo[r], hi = sHi[r];
            float4 s = make_float4(0.f, 0.f, 0.f, 0.f);
            for (int e = lo; e < hi; e++) {
                float4 v = ld4(g_efeat + (size_t)e * DD + c4);
                s.x += v.x; s.y += v.y; s.z += v.z; s.w += v.w;
            }
            conv_store2(Ahi, Alo, r, c4,     s.x, s.y);
            conv_store2(Ahi, Alo, r, c4 + 2, s.z, s.w);
        }
    }
    copy_wimg(sm, 5);                       // Wn0 rows [128:256)
    __syncthreads();

    float acc[16][4];
    zero_acc(acc);
    gemm3(smem, wid, lane, acc);            // agg @ Wn0[128:256)
    __syncthreads();

    stage_A(Ahi, Alo, grid, n0, rv);
    copy_wimg(sm, 4);                       // Wn0 rows [0:128)
    __syncthreads();
    gemm3(smem, wid, lane, acc);            // += grid @ Wn0[0:128)

    // silu(+bn0) -> h into A tiles (own rows)
    int r0l = wid * 16 + gid, r1l = r0l + 8;
    __syncthreads();                        // all warps done reading A (grid tile)
    #pragma unroll
    for (int nf = 0; nf < 16; nf++) {
        int col = nf * 8 + tg * 2;
        float2 bb = ld2(bn0 + col);
        conv_store2(Ahi, Alo, r0l, col, silu_f(acc[nf][0] + bb.x), silu_f(acc[nf][1] + bb.y));
        conv_store2(Ahi, Alo, r1l, col, silu_f(acc[nf][2] + bb.x), silu_f(acc[nf][3] + bb.y));
    }
    __syncthreads();
    copy_wimg(sm, 6);                       // Wn1
    __syncthreads();

    zero_acc(acc);
    gemm3(smem, wid, lane, acc);            // h @ Wn1

    // +bn1, LayerNorm, +grid residual, store
    int r0 = n0 + r0l, r1 = n0 + r1l;
    bool v0 = r0 < N_GRID_C, v1 = r1 < N_GRID_C;
    float s1a = 0.f, s2a = 0.f, s1b = 0.f, s2b = 0.f;
    #pragma unroll
    for (int nf = 0; nf < 16; nf++) {
        int col = nf * 8 + tg * 2;
        float2 bb = ld2(bn1 + col);
        acc[nf][0] += bb.x; acc[nf][1] += bb.y;
        acc[nf][2] += bb.x; acc[nf][3] += bb.y;
        s1a += acc[nf][0] + acc[nf][1];
        s2a += acc[nf][0]*acc[nf][0] + acc[nf][1]*acc[nf][1];
        s1b += acc[nf][2] + acc[nf][3];
        s2b += acc[nf][2]*acc[nf][2] + acc[nf][3]*acc[nf][3];
    }
    s1a = qsum(s1a); s2a = qsum(s2a); s1b = qsum(s1b); s2b = qsum(s2b);
    float mu0 = s1a * 0.0078125f, rstd0 = rsqrtf(s2a * 0.0078125f - mu0*mu0 + 1e-5f);
    float mu1 = s1b * 0.0078125f, rstd1 = rsqrtf(s2b * 0.0078125f - mu1*mu1 + 1e-5f);
    #pragma unroll
    for (int nf = 0; nf < 16; nf++) {
        int col = nf * 8 + tg * 2;
        float2 gv = ld2(gn + col), bv = ld2(bnv + col);
        if (v0) {
            float2 gr = ld2(grid + (size_t)r0 * DD + col);
            *reinterpret_cast<float2*>(out + (size_t)r0 * DD + col) =
                make_float2((acc[nf][0]-mu0)*rstd0*gv.x + bv.x + gr.x,
                            (acc[nf][1]-mu0)*rstd0*gv.y + bv.y + gr.y);
        }
        if (v1) {
            float2 gr = ld2(grid + (size_t)r1 * DD + col);
            *reinterpret_cast<float2*>(out + (size_t)r1 * DD + col) =
                make_float2((acc[nf][2]-mu1)*rstd1*gv.x + bv.x + gr.x,
                            (acc[nf][3]-mu1)*rstd1*gv.y + bv.y + gr.y);
        }
    }
}

// -------------------- launch -------------------------------------------------
extern "C" void kernel_launch(void* const* d_in, const int* in_sizes, int n_in,
                              void* d_out, int out_size) {
    (void)in_sizes; (void)n_in; (void)out_size;

    const float* m2g  = (const float*)d_in[0];
    const float* grid = (const float*)d_in[1];
    const float* mesh = (const float*)d_in[2];
    const int*   src  = (const int*)  d_in[3];
    const int*   dst  = (const int*)  d_in[4];
    const float* We   = (const float*)d_in[5];
    const float* Ws   = (const float*)d_in[6];
    const float* Wd   = (const float*)d_in[7];
    const float* b0   = (const float*)d_in[8];
    const float* W1e  = (const float*)d_in[9];
    const float* b1e  = (const float*)d_in[10];
    const float* ge   = (const float*)d_in[11];
    const float* be   = (const float*)d_in[12];
    const float* Wn0  = (const float*)d_in[13];
    const float* bn0  = (const float*)d_in[14];
    const float* Wn1  = (const float*)d_in[15];
    const float* bn1  = (const float*)d_in[16];
    const float* gn   = (const float*)d_in[17];
    const float* bn   = (const float*)d_in[18];
    float* out = (float*)d_out;

    cudaFuncSetAttribute(proj_mm, cudaFuncAttributeMaxDynamicSharedMemorySize, SM_TOTAL);
    cudaFuncSetAttribute(edge_mm, cudaFuncAttributeMaxDynamicSharedMemorySize, SM_TOTAL);
    cudaFuncSetAttribute(node_mm, cudaFuncAttributeMaxDynamicSharedMemorySize, SM_TOTAL);

    void *pm = nullptr, *pg = nullptr;
    cudaGetSymbolAddress(&pm, g_Pmesh);
    cudaGetSymbolAddress(&pg, g_Pgrid);

    convw_kernel<<<7, 256>>>(Ws, Wd, We, W1e, Wn0, Wn1);

    int gb_mesh = (N_MESH_C + TILE_M - 1) / TILE_M;
    int gb_grid = (N_GRID_C + TILE_M - 1) / TILE_M;
    int gb_edge = (N_EDGE_C + TILE_M - 1) / TILE_M;

    proj_mm<<<gb_mesh, NT, SM_TOTAL>>>(mesh, 0, (float*)pm, N_MESH_C);
    proj_mm<<<gb_grid, NT, SM_TOTAL>>>(grid, 1, (float*)pg, N_GRID_C);
    edge_mm<<<gb_edge, NT, SM_TOTAL>>>(m2g, src, dst, b0, b1e, ge, be);
    node_mm<<<gb_grid, NT, SM_TOTAL>>>(grid, dst, bn0, bn1, gn, bn, out);
}

// round 14
// speedup vs baseline: 2.5191x; 2.1248x over previous
#include <cuda_runtime.h>
#include <cuda_bf16.h>
#include <cstdint>

#define DD       128
#define NT       128                      // 4 warps per CTA
#define TILE_M   64                       // rows per CTA tile (16 per warp)
#define WSROW    136                      // padded bf16 row stride (272 B)
#define N_MESH_C 40962
#define N_GRID_C 200000
#define N_EDGE_C 600000

// shared memory: A hi/lo planes only. 64 x 136 bf16 = 17408 B each.
#define SM_AHI   0
#define SM_ALO   17408
#define SM_TOTAL 34816                    // ~35KB -> 3+ CTAs/SM

#define WIMG_ELEMS (2 * DD * WSROW)       // staging layout for convw (hi+lo planes)

// -------------------- global scratch (allocation-free) ----------------------
// Fragment-ordered weight images: [widx][plane][ks][p][lane] as uint4.
// 7 weights x 2 planes x 64 (ks*8+p) x 32 lanes x 16B = 448 KB.
__device__ uint4 g_Wfrag[7 * 4096];
__device__ __align__(16) float g_Pmesh[(size_t)N_MESH_C * DD];
__device__ __align__(16) float g_Pgrid[(size_t)N_GRID_C * DD];
__device__ __align__(16) float g_efeat[(size_t)N_EDGE_C * DD];

// -------------------- helpers ----------------------------------------------
__device__ __forceinline__ float4 ld4(const float* p) { return *reinterpret_cast<const float4*>(p); }
__device__ __forceinline__ float2 ld2(const float* p) { return *reinterpret_cast<const float2*>(p); }
__device__ __forceinline__ float silu_f(float x) { return x / (1.0f + __expf(-x)); }
__device__ __forceinline__ float qsum(float v) {
    v += __shfl_xor_sync(0xffffffffu, v, 1);
    v += __shfl_xor_sync(0xffffffffu, v, 2);
    return v;
}
__device__ __forceinline__ uint32_t s2u(const void* p) {
    uint32_t a;
    asm("{ .reg .u64 t; cvta.to.shared.u64 t, %1; cvt.u32.u64 %0, t; }" : "=r"(a) : "l"(p));
    return a;
}
__device__ __forceinline__ uint32_t packbf2(float x, float y) {
    __nv_bfloat162 t = __floats2bfloat162_rn(x, y);
    return *reinterpret_cast<uint32_t*>(&t);
}
// split-bf16 store of 2 consecutive k values at warp-local row r into hi/lo planes
__device__ __forceinline__ void conv_store2(char* Thi, char* Tlo, int r, int k, float x, float y) {
    __nv_bfloat16 hx = __float2bfloat16(x), hy = __float2bfloat16(y);
    float rx = x - __bfloat162float(hx), ry = y - __bfloat162float(hy);
    uint32_t off = (uint32_t)r * (WSROW * 2) + (uint32_t)k * 2;
    *reinterpret_cast<uint32_t*>(Thi + off) = packbf2(__bfloat162float(hx), __bfloat162float(hy));
    *reinterpret_cast<uint32_t*>(Tlo + off) = packbf2(rx, ry);
}

// Per-warp stage: warp stages ITS OWN 16 rows (16w .. 16w+15) from gsrc.
__device__ __forceinline__ void stage_warpA(char* wAhi, char* wAlo, const float* gsrc,
                                            int grow0, int M, int lane) {
    int c4 = lane * 4;
    #pragma unroll
    for (int i = 0; i < 16; i++) {
        int gr = grow0 + i;
        float4 v = make_float4(0.f, 0.f, 0.f, 0.f);
        if (gr < M) v = ld4(gsrc + (size_t)gr * DD + c4);
        conv_store2(wAhi, wAlo, i, c4,     v.x, v.y);
        conv_store2(wAhi, wAlo, i, c4 + 2, v.z, v.w);
    }
}

// -------------------- mma.sync core -----------------------------------------
#define MMA_BF16(acc, a0, a1, a2, a3, b0, b1) \
    asm volatile("mma.sync.aligned.m16n8k16.row.col.f32.bf16.bf16.f32 " \
                 "{%0,%1,%2,%3}, {%4,%5,%6,%7}, {%8,%9}, {%0,%1,%2,%3};" \
                 : "+f"((acc)[0]), "+f"((acc)[1]), "+f"((acc)[2]), "+f"((acc)[3]) \
                 : "r"(a0), "r"(a1), "r"(a2), "r"(a3), "r"(b0), "r"(b1))

// 3-term split accumulation, B-frags via LDG from fragment-ordered image:
//   group 1 (B = Wh): (Ah + Al) @ Wh      group 2 (B = Wl): Ah @ Wl
__device__ __forceinline__ void gemm3(uint32_t aHi, uint32_t aLo,
                                      const uint4* __restrict__ Wf, float acc[16][4]) {
    // group 1
    #pragma unroll
    for (int ks = 0; ks < 8; ks++) {
        uint32_t h0, h1, h2, h3, l0, l1, l2, l3;
        asm volatile("ldmatrix.sync.aligned.m8n8.x4.shared.b16 {%0,%1,%2,%3}, [%4];"
                     : "=r"(h0), "=r"(h1), "=r"(h2), "=r"(h3) : "r"(aHi + ks * 32));
        asm volatile("ldmatrix.sync.aligned.m8n8.x4.shared.b16 {%0,%1,%2,%3}, [%4];"
                     : "=r"(l0), "=r"(l1), "=r"(l2), "=r"(l3) : "r"(aLo + ks * 32));
        #pragma unroll
        for (int p = 0; p < 8; p++) {
            uint4 b = __ldg(Wf + (ks * 8 + p) * 32);
            MMA_BF16(acc[2*p],   h0, h1, h2, h3, b.x, b.y);
            MMA_BF16(acc[2*p+1], h0, h1, h2, h3, b.z, b.w);
            MMA_BF16(acc[2*p],   l0, l1, l2, l3, b.x, b.y);
            MMA_BF16(acc[2*p+1], l0, l1, l2, l3, b.z, b.w);
        }
    }
    // group 2
    #pragma unroll
    for (int ks = 0; ks < 8; ks++) {
        uint32_t h0, h1, h2, h3;
        asm volatile("ldmatrix.sync.aligned.m8n8.x4.shared.b16 {%0,%1,%2,%3}, [%4];"
                     : "=r"(h0), "=r"(h1), "=r"(h2), "=r"(h3) : "r"(aHi + ks * 32));
        #pragma unroll
        for (int p = 0; p < 8; p++) {
            uint4 b = __ldg(Wf + 2048 + (ks * 8 + p) * 32);
            MMA_BF16(acc[2*p],   h0, h1, h2, h3, b.x, b.y);
            MMA_BF16(acc[2*p+1], h0, h1, h2, h3, b.z, b.w);
        }
    }
}

__device__ __forceinline__ void zero_acc(float acc[16][4]) {
    #pragma unroll
    for (int i = 0; i < 16; i++) {
        acc[i][0] = 0.f; acc[i][1] = 0.f; acc[i][2] = 0.f; acc[i][3] = 0.f;
    }
}

// A-frag ldmatrix lane offset within a warp's private 16-row block
__device__ __forceinline__ uint32_t a_lane_off(int lane) {
    return (uint32_t)(lane & 15) * (WSROW * 2) + (uint32_t)(lane >> 4) * 16;
}

// -------------------- weight pre-conversion ---------------------------------
// Stage W^T split-bf16 into smem exactly like the old layout, then run the SAME
// ldmatrix pattern the old gemm used and dump the registers to g_Wfrag.
// blockIdx: 0:Ws 1:Wd 2:We 3:W1e 4:Wn0[0:128) 5:Wn0[128:256) 6:Wn1
__global__ void convw_kernel(const float* __restrict__ Ws, const float* __restrict__ Wd,
                             const float* __restrict__ We, const float* __restrict__ W1e,
                             const float* __restrict__ Wn0, const float* __restrict__ Wn1) {
    extern __shared__ char sm[];
    uint32_t smem = s2u(sm);
    int b = blockIdx.x;
    const float* src; int roff = 0;
    switch (b) {
        case 0: src = Ws;  break;
        case 1: src = Wd;  break;
        case 2: src = We;  break;
        case 3: src = W1e; break;
        case 4: src = Wn0; break;
        case 5: src = Wn0; roff = 128; break;
        default: src = Wn1; break;
    }
    __nv_bfloat16* hi = (__nv_bfloat16*)sm;
    __nv_bfloat16* lo = hi + DD * WSROW;
    for (int idx = threadIdx.x; idx < DD * DD; idx += 256) {
        int n = idx >> 7, k = idx & 127;
        float x = src[(size_t)(roff + k) * DD + n];
        __nv_bfloat16 h = __float2bfloat16(x);
        hi[n * WSROW + k] = h;
        lo[n * WSROW + k] = __float2bfloat16(x - __bfloat162float(h));
    }
    __syncthreads();

    if (threadIdx.x < 32) {
        int lane = threadIdx.x;
        uint32_t boff = ((uint32_t)((lane & 7) + ((lane >> 4) << 3))) * (WSROW * 2)
                      + (uint32_t)((lane >> 3) & 1) * 16;
        #pragma unroll 1
        for (int plane = 0; plane < 2; plane++) {
            uint32_t base = smem + (uint32_t)plane * (DD * WSROW * 2) + boff;
            for (int ks = 0; ks < 8; ks++) {
                for (int p = 0; p < 8; p++) {
                    uint32_t b0, b1, b2, b3;
                    asm volatile("ldmatrix.sync.aligned.m8n8.x4.shared.b16 {%0,%1,%2,%3}, [%4];"
                                 : "=r"(b0), "=r"(b1), "=r"(b2), "=r"(b3)
                                 : "r"(base + p * (16 * WSROW * 2) + ks * 32));
                    g_Wfrag[b * 4096 + (plane * 64 + ks * 8 + p) * 32 + lane] =
                        make_uint4(b0, b1, b2, b3);
                }
            }
        }
    }
}

// -------------------- proj: C = A @ W ---------------------------------------
__global__ void __launch_bounds__(NT, 3)
proj_mm(const float* __restrict__ A, int widx, float* __restrict__ C, int M) {
    extern __shared__ char sm[];
    uint32_t smem = s2u(sm);
    int tid = threadIdx.x, wid = tid >> 5, lane = tid & 31;
    int gid = lane >> 2, tg = lane & 3;
    int m0 = blockIdx.x * TILE_M;

    char* wAhi = sm + SM_AHI + wid * 16 * (WSROW * 2);
    char* wAlo = sm + SM_ALO + wid * 16 * (WSROW * 2);
    stage_warpA(wAhi, wAlo, A, m0 + wid * 16, M, lane);
    __syncwarp();

    uint32_t aHi = smem + SM_AHI + (uint32_t)wid * 16 * (WSROW * 2) + a_lane_off(lane);
    uint32_t aLo = aHi + (SM_ALO - SM_AHI);
    const uint4* Wf = g_Wfrag + widx * 4096 + lane;

    float acc[16][4];
    zero_acc(acc);
    gemm3(aHi, aLo, Wf, acc);

    int r0 = m0 + wid * 16 + gid, r1 = r0 + 8;
    #pragma unroll
    for (int nf = 0; nf < 16; nf++) {
        int col = nf * 8 + tg * 2;
        if (r0 < M) *reinterpret_cast<float2*>(C + (size_t)r0 * DD + col) = make_float2(acc[nf][0], acc[nf][1]);
        if (r1 < M) *reinterpret_cast<float2*>(C + (size_t)r1 * DD + col) = make_float2(acc[nf][2], acc[nf][3]);
    }
}

// -------------------- edge kernel (sync-free) --------------------------------
__global__ void __launch_bounds__(NT, 3)
edge_mm(const float* __restrict__ m2g, const int* __restrict__ src, const int* __restrict__ dst,
        const float* __restrict__ b0, const float* __restrict__ b1e,
        const float* __restrict__ ge, const float* __restrict__ be) {
    extern __shared__ char sm[];
    uint32_t smem = s2u(sm);
    int tid = threadIdx.x, wid = tid >> 5, lane = tid & 31;
    int gid = lane >> 2, tg = lane & 3;
    int e0 = blockIdx.x * TILE_M;

    char* wAhi = sm + SM_AHI + wid * 16 * (WSROW * 2);
    char* wAlo = sm + SM_ALO + wid * 16 * (WSROW * 2);
    stage_warpA(wAhi, wAlo, m2g, e0 + wid * 16, N_EDGE_C, lane);
    __syncwarp();

    uint32_t aHi = smem + SM_AHI + (uint32_t)wid * 16 * (WSROW * 2) + a_lane_off(lane);
    uint32_t aLo = aHi + (SM_ALO - SM_AHI);

    // pre-init acc with Pmesh[src] + Pgrid[dst] + b0 (long-latency LDGs up front)
    int r0l = wid * 16 + gid, r1l = r0l + 8;
    int er0 = e0 + r0l, er1 = e0 + r1l;
    int s0 = __ldg(src + er0), d0 = __ldg(dst + er0);
    int s1 = __ldg(src + er1), d1 = __ldg(dst + er1);

    float acc[16][4];
    #pragma unroll
    for (int nf = 0; nf < 16; nf++) {
        int col = nf * 8 + tg * 2;
        float2 bb = ld2(b0 + col);
        float2 pm0 = ld2(g_Pmesh + (size_t)s0 * DD + col);
        float2 pg0 = ld2(g_Pgrid + (size_t)d0 * DD + col);
        float2 pm1 = ld2(g_Pmesh + (size_t)s1 * DD + col);
        float2 pg1 = ld2(g_Pgrid + (size_t)d1 * DD + col);
        acc[nf][0] = bb.x + pm0.x + pg0.x;
        acc[nf][1] = bb.y + pm0.y + pg0.y;
        acc[nf][2] = bb.x + pm1.x + pg1.x;
        acc[nf][3] = bb.y + pm1.y + pg1.y;
    }

    gemm3(aHi, aLo, g_Wfrag + 2 * 4096 + lane, acc);     // += m2g @ We

    // silu -> h back into this warp's own A rows
    #pragma unroll
    for (int nf = 0; nf < 16; nf++) {
        int col = nf * 8 + tg * 2;
        conv_store2(wAhi, wAlo, gid,     col, silu_f(acc[nf][0]), silu_f(acc[nf][1]));
        conv_store2(wAhi, wAlo, gid + 8, col, silu_f(acc[nf][2]), silu_f(acc[nf][3]));
    }
    __syncwarp();

    zero_acc(acc);
    gemm3(aHi, aLo, g_Wfrag + 3 * 4096 + lane, acc);     // h @ W1e

    // +b1e, LayerNorm (warp owns full rows), store efeat
    float s1a = 0.f, s2a = 0.f, s1b = 0.f, s2b = 0.f;
    #pragma unroll
    for (int nf = 0; nf < 16; nf++) {
        int col = nf * 8 + tg * 2;
        float2 bb = ld2(b1e + col);
        acc[nf][0] += bb.x; acc[nf][1] += bb.y;
        acc[nf][2] += bb.x; acc[nf][3] += bb.y;
        s1a += acc[nf][0] + acc[nf][1];
        s2a += acc[nf][0]*acc[nf][0] + acc[nf][1]*acc[nf][1];
        s1b += acc[nf][2] + acc[nf][3];
        s2b += acc[nf][2]*acc[nf][2] + acc[nf][3]*acc[nf][3];
    }
    s1a = qsum(s1a); s2a = qsum(s2a); s1b = qsum(s1b); s2b = qsum(s2b);
    float mu0 = s1a * 0.0078125f, rstd0 = rsqrtf(s2a * 0.0078125f - mu0*mu0 + 1e-5f);
    float mu1 = s1b * 0.0078125f, rstd1 = rsqrtf(s2b * 0.0078125f - mu1*mu1 + 1e-5f);
    #pragma unroll
    for (int nf = 0; nf < 16; nf++) {
        int col = nf * 8 + tg * 2;
        float2 gv = ld2(ge + col), bv = ld2(be + col);
        *reinterpret_cast<float2*>(g_efeat + (size_t)er0 * DD + col) =
            make_float2((acc[nf][0]-mu0)*rstd0*gv.x + bv.x, (acc[nf][1]-mu0)*rstd0*gv.y + bv.y);
        *reinterpret_cast<float2*>(g_efeat + (size_t)er1 * DD + col) =
            make_float2((acc[nf][2]-mu1)*rstd1*gv.x + bv.x, (acc[nf][3]-mu1)*rstd1*gv.y + bv.y);
    }
}

// -------------------- node kernel (sync-free) --------------------------------
__global__ void __launch_bounds__(NT, 3)
node_mm(const float* __restrict__ grid, const int* __restrict__ dst,
        const float* __restrict__ bn0, const float* __restrict__ bn1,
        const float* __restrict__ gn, const float* __restrict__ bnv,
        float* __restrict__ out) {
    extern __shared__ char sm[];
    uint32_t smem = s2u(sm);
    int tid = threadIdx.x, wid = tid >> 5, lane = tid & 31;
    int gid = lane >> 2, tg = lane & 3;
    int n0 = blockIdx.x * TILE_M;

    // per-row edge ranges in lane registers (dst sorted); lane<16 owns row 16w+lane
    int myLo = 0, myHi = 0;
    if (lane < 16) {
        int n = n0 + wid * 16 + lane;
        int lo = 0, hi = N_EDGE_C;
        while (lo < hi) { int m = (lo + hi) >> 1; if (__ldg(dst + m) <  n) lo = m + 1; else hi = m; }
        myLo = lo;
        int lo2 = lo, hi2 = N_EDGE_C;
        while (lo2 < hi2) { int m = (lo2 + hi2) >> 1; if (__ldg(dst + m) <= n) lo2 = m + 1; else hi2 = m; }
        myHi = lo2;
    }

    char* wAhi = sm + SM_AHI + wid * 16 * (WSROW * 2);
    char* wAlo = sm + SM_ALO + wid * 16 * (WSROW * 2);
    uint32_t aHi = smem + SM_AHI + (uint32_t)wid * 16 * (WSROW * 2) + a_lane_off(lane);
    uint32_t aLo = aHi + (SM_ALO - SM_AHI);

    // pass 1: grid tile @ Wn0[0:128)
    stage_warpA(wAhi, wAlo, grid, n0 + wid * 16, N_GRID_C, lane);
    __syncwarp();
    float acc[16][4];
    zero_acc(acc);
    gemm3(aHi, aLo, g_Wfrag + 4 * 4096 + lane, acc);

    // pass 2: segment-sum into own A rows, then @ Wn0[128:256)
    {
        int c4 = lane * 4;
        #pragma unroll 1
        for (int i = 0; i < 16; i++) {
            int lo = __shfl_sync(0xffffffffu, myLo, i);
            int hi = __shfl_sync(0xffffffffu, myHi, i);
            float4 s = make_float4(0.f, 0.f, 0.f, 0.f);
            for (int e = lo; e < hi; e++) {
                float4 v = ld4(g_efeat + (size_t)e * DD + c4);
                s.x += v.x; s.y += v.y; s.z += v.z; s.w += v.w;
            }
            conv_store2(wAhi, wAlo, i, c4,     s.x, s.y);
            conv_store2(wAhi, wAlo, i, c4 + 2, s.z, s.w);
        }
    }
    __syncwarp();
    gemm3(aHi, aLo, g_Wfrag + 5 * 4096 + lane, acc);     // accumulate

    // silu(+bn0) -> h into own A rows
    #pragma unroll
    for (int nf = 0; nf < 16; nf++) {
        int col = nf * 8 + tg * 2;
        float2 bb = ld2(bn0 + col);
        conv_store2(wAhi, wAlo, gid,     col, silu_f(acc[nf][0] + bb.x), silu_f(acc[nf][1] + bb.y));
        conv_store2(wAhi, wAlo, gid + 8, col, silu_f(acc[nf][2] + bb.x), silu_f(acc[nf][3] + bb.y));
    }
    __syncwarp();

    zero_acc(acc);
    gemm3(aHi, aLo, g_Wfrag + 6 * 4096 + lane, acc);     // h @ Wn1

    // +bn1, LayerNorm, +grid residual, store
    int r0 = n0 + wid * 16 + gid, r1 = r0 + 8;
    float s1a = 0.f, s2a = 0.f, s1b = 0.f, s2b = 0.f;
    #pragma unroll
    for (int nf = 0; nf < 16; nf++) {
        int col = nf * 8 + tg * 2;
        float2 bb = ld2(bn1 + col);
        acc[nf][0] += bb.x; acc[nf][1] += bb.y;
        acc[nf][2] += bb.x; acc[nf][3] += bb.y;
        s1a += acc[nf][0] + acc[nf][1];
        s2a += acc[nf][0]*acc[nf][0] + acc[nf][1]*acc[nf][1];
        s1b += acc[nf][2] + acc[nf][3];
        s2b += acc[nf][2]*acc[nf][2] + acc[nf][3]*acc[nf][3];
    }
    s1a = qsum(s1a); s2a = qsum(s2a); s1b = qsum(s1b); s2b = qsum(s2b);
    float mu0 = s1a * 0.0078125f, rstd0 = rsqrtf(s2a * 0.0078125f - mu0*mu0 + 1e-5f);
    float mu1 = s1b * 0.0078125f, rstd1 = rsqrtf(s2b * 0.0078125f - mu1*mu1 + 1e-5f);
    #pragma unroll
    for (int nf = 0; nf < 16; nf++) {
        int col = nf * 8 + tg * 2;
        float2 gv = ld2(gn + col), bv = ld2(bnv + col);
        float2 gr0 = ld2(grid + (size_t)r0 * DD + col);
        float2 gr1 = ld2(grid + (size_t)r1 * DD + col);
        *reinterpret_cast<float2*>(out + (size_t)r0 * DD + col) =
            make_float2((acc[nf][0]-mu0)*rstd0*gv.x + bv.x + gr0.x,
                        (acc[nf][1]-mu0)*rstd0*gv.y + bv.y + gr0.y);
        *reinterpret_cast<float2*>(out + (size_t)r1 * DD + col) =
            make_float2((acc[nf][2]-mu1)*rstd1*gv.x + bv.x + gr1.x,
                        (acc[nf][3]-mu1)*rstd1*gv.y + bv.y + gr1.y);
    }
}

// -------------------- launch -------------------------------------------------
extern "C" void kernel_launch(void* const* d_in, const int* in_sizes, int n_in,
                              void* d_out, int out_size) {
    (void)in_sizes; (void)n_in; (void)out_size;

    const float* m2g  = (const float*)d_in[0];
    const float* grid = (const float*)d_in[1];
    const float* mesh = (const float*)d_in[2];
    const int*   src  = (const int*)  d_in[3];
    const int*   dst  = (const int*)  d_in[4];
    const float* We   = (const float*)d_in[5];
    const float* Ws   = (const float*)d_in[6];
    const float* Wd   = (const float*)d_in[7];
    const float* b0   = (const float*)d_in[8];
    const float* W1e  = (const float*)d_in[9];
    const float* b1e  = (const float*)d_in[10];
    const float* ge   = (const float*)d_in[11];
    const float* be   = (const float*)d_in[12];
    const float* Wn0  = (const float*)d_in[13];
    const float* bn0  = (const float*)d_in[14];
    const float* Wn1  = (const float*)d_in[15];
    const float* bn1  = (const float*)d_in[16];
    const float* gn   = (const float*)d_in[17];
    const float* bn   = (const float*)d_in[18];
    float* out = (float*)d_out;

    const int CONVW_SMEM = 2 * DD * WSROW * 2;  // 69632
    cudaFuncSetAttribute(convw_kernel, cudaFuncAttributeMaxDynamicSharedMemorySize, CONVW_SMEM);
    cudaFuncSetAttribute(proj_mm, cudaFuncAttributeMaxDynamicSharedMemorySize, SM_TOTAL);
    cudaFuncSetAttribute(edge_mm, cudaFuncAttributeMaxDynamicSharedMemorySize, SM_TOTAL);
    cudaFuncSetAttribute(node_mm, cudaFuncAttributeMaxDynamicSharedMemorySize, SM_TOTAL);

    void *pm = nullptr, *pg = nullptr;
    cudaGetSymbolAddress(&pm, g_Pmesh);
    cudaGetSymbolAddress(&pg, g_Pgrid);

    convw_kernel<<<7, 256, CONVW_SMEM>>>(Ws, Wd, We, W1e, Wn0, Wn1);

    int gb_mesh = (N_MESH_C + TILE_M - 1) / TILE_M;
    int gb_grid = (N_GRID_C + TILE_M - 1) / TILE_M;
    int gb_edge = (N_EDGE_C + TILE_M - 1) / TILE_M;

    proj_mm<<<gb_mesh, NT, SM_TOTAL>>>(mesh, 0, (float*)pm, N_MESH_C);
    proj_mm<<<gb_grid, NT, SM_TOTAL>>>(grid, 1, (float*)pg, N_GRID_C);
    edge_mm<<<gb_edge, NT, SM_TOTAL>>>(m2g, src, dst, b0, b1e, ge, be);
    node_mm<<<gb_grid, NT, SM_TOTAL>>>(grid, dst, bn0, bn1, gn, bn, out);
}

// round 15
// speedup vs baseline: 3.0778x; 1.2218x over previous
#include <cuda_runtime.h>
#include <cuda_fp16.h>
#include <cstdint>

#define DD       128
#define NT       128                      // 4 warps per CTA
#define TILE_M   64                       // rows per CTA tile (16 per warp)
#define WSROW    136                      // padded fp16 row stride (272 B)
#define N_MESH_C 40962
#define N_GRID_C 200000
#define N_EDGE_C 600000

// shared memory: A hi/lo planes only. 64 x 136 fp16 = 17408 B each.
#define SM_AHI   0
#define SM_ALO   17408
#define SM_TOTAL 34816                    // ~35KB -> 3 CTAs/SM

// -------------------- global scratch (allocation-free) ----------------------
// Fragment-ordered weight images (hi plane only): [widx][ks*8+p][lane] uint4.
// 7 weights x 64 x 32 x 16B = 224 KB total (32 KB per weight, L1-resident).
__device__ uint4 g_Wfrag[7 * 2048];
__device__ __align__(16) float g_Pmesh[(size_t)N_MESH_C * DD];
__device__ __align__(16) float g_Pgrid[(size_t)N_GRID_C * DD];
__device__ __align__(16) float g_efeat[(size_t)N_EDGE_C * DD];

// -------------------- helpers ----------------------------------------------
__device__ __forceinline__ float4 ld4(const float* p) { return *reinterpret_cast<const float4*>(p); }
__device__ __forceinline__ float2 ld2(const float* p) { return *reinterpret_cast<const float2*>(p); }
__device__ __forceinline__ float silu_f(float x) { return x / (1.0f + __expf(-x)); }
__device__ __forceinline__ float qsum(float v) {
    v += __shfl_xor_sync(0xffffffffu, v, 1);
    v += __shfl_xor_sync(0xffffffffu, v, 2);
    return v;
}
__device__ __forceinline__ uint32_t s2u(const void* p) {
    uint32_t a;
    asm("{ .reg .u64 t; cvta.to.shared.u64 t, %1; cvt.u32.u64 %0, t; }" : "=r"(a) : "l"(p));
    return a;
}
__device__ __forceinline__ uint32_t packh2(float x, float y) {
    __half2 t = __floats2half2_rn(x, y);
    return *reinterpret_cast<uint32_t*>(&t);
}
// split-fp16 store of 2 consecutive k values at warp-local row r into hi/lo planes
__device__ __forceinline__ void conv_store2(char* Thi, char* Tlo, int r, int k, float x, float y) {
    float hx = __half2float(__float2half_rn(x));
    float hy = __half2float(__float2half_rn(y));
    uint32_t off = (uint32_t)r * (WSROW * 2) + (uint32_t)k * 2;
    *reinterpret_cast<uint32_t*>(Thi + off) = packh2(hx, hy);
    *reinterpret_cast<uint32_t*>(Tlo + off) = packh2(x - hx, y - hy);
}

// Per-warp stage: warp stages ITS OWN 16 rows (16w .. 16w+15) from gsrc.
__device__ __forceinline__ void stage_warpA(char* wAhi, char* wAlo, const float* gsrc,
                                            int grow0, int M, int lane) {
    int c4 = lane * 4;
    #pragma unroll
    for (int i = 0; i < 16; i++) {
        int gr = grow0 + i;
        float4 v = make_float4(0.f, 0.f, 0.f, 0.f);
        if (gr < M) v = ld4(gsrc + (size_t)gr * DD + c4);
        conv_store2(wAhi, wAlo, i, c4,     v.x, v.y);
        conv_store2(wAhi, wAlo, i, c4 + 2, v.z, v.w);
    }
}

// -------------------- mma.sync core -----------------------------------------
#define MMA_F16(acc, a0, a1, a2, a3, b0, b1) \
    asm volatile("mma.sync.aligned.m16n8k16.row.col.f32.f16.f16.f32 " \
                 "{%0,%1,%2,%3}, {%4,%5,%6,%7}, {%8,%9}, {%0,%1,%2,%3};" \
                 : "+f"((acc)[0]), "+f"((acc)[1]), "+f"((acc)[2]), "+f"((acc)[3]) \
                 : "r"(a0), "r"(a1), "r"(a2), "r"(a3), "r"(b0), "r"(b1))

// 2-term split accumulation: (Ah + Al) @ Wh.  B-frags via LDG (L1-resident).
__device__ __forceinline__ void gemm2(uint32_t aHi, uint32_t aLo,
                                      const uint4* __restrict__ Wf, float acc[16][4]) {
    #pragma unroll
    for (int ks = 0; ks < 8; ks++) {
        uint32_t h0, h1, h2, h3, l0, l1, l2, l3;
        asm volatile("ldmatrix.sync.aligned.m8n8.x4.shared.b16 {%0,%1,%2,%3}, [%4];"
                     : "=r"(h0), "=r"(h1), "=r"(h2), "=r"(h3) : "r"(aHi + ks * 32));
        asm volatile("ldmatrix.sync.aligned.m8n8.x4.shared.b16 {%0,%1,%2,%3}, [%4];"
                     : "=r"(l0), "=r"(l1), "=r"(l2), "=r"(l3) : "r"(aLo + ks * 32));
        #pragma unroll
        for (int p = 0; p < 8; p++) {
            uint4 b = __ldg(Wf + (ks * 8 + p) * 32);
            MMA_F16(acc[2*p],   h0, h1, h2, h3, b.x, b.y);
            MMA_F16(acc[2*p+1], h0, h1, h2, h3, b.z, b.w);
            MMA_F16(acc[2*p],   l0, l1, l2, l3, b.x, b.y);
            MMA_F16(acc[2*p+1], l0, l1, l2, l3, b.z, b.w);
        }
    }
}

__device__ __forceinline__ void zero_acc(float acc[16][4]) {
    #pragma unroll
    for (int i = 0; i < 16; i++) {
        acc[i][0] = 0.f; acc[i][1] = 0.f; acc[i][2] = 0.f; acc[i][3] = 0.f;
    }
}

// A-frag ldmatrix lane offset within a warp's private 16-row block
__device__ __forceinline__ uint32_t a_lane_off(int lane) {
    return (uint32_t)(lane & 15) * (WSROW * 2) + (uint32_t)(lane >> 4) * 16;
}

// -------------------- weight pre-conversion ---------------------------------
// Stage W^T (fp16 hi plane) into smem with the gemm layout, run the SAME
// ldmatrix pattern the gemm uses, dump the registers to g_Wfrag.
// blockIdx: 0:Ws 1:Wd 2:We 3:W1e 4:Wn0[0:128) 5:Wn0[128:256) 6:Wn1
__global__ void convw_kernel(const float* __restrict__ Ws, const float* __restrict__ Wd,
                             const float* __restrict__ We, const float* __restrict__ W1e,
                             const float* __restrict__ Wn0, const float* __restrict__ Wn1) {
    extern __shared__ char sm[];
    uint32_t smem = s2u(sm);
    int b = blockIdx.x;
    const float* src; int roff = 0;
    switch (b) {
        case 0: src = Ws;  break;
        case 1: src = Wd;  break;
        case 2: src = We;  break;
        case 3: src = W1e; break;
        case 4: src = Wn0; break;
        case 5: src = Wn0; roff = 128; break;
        default: src = Wn1; break;
    }
    __half* hi = (__half*)sm;
    for (int idx = threadIdx.x; idx < DD * DD; idx += 256) {
        int n = idx >> 7, k = idx & 127;
        hi[n * WSROW + k] = __float2half_rn(src[(size_t)(roff + k) * DD + n]);
    }
    __syncthreads();

    if (threadIdx.x < 32) {
        int lane = threadIdx.x;
        uint32_t boff = ((uint32_t)((lane & 7) + ((lane >> 4) << 3))) * (WSROW * 2)
                      + (uint32_t)((lane >> 3) & 1) * 16;
        for (int ks = 0; ks < 8; ks++) {
            for (int p = 0; p < 8; p++) {
                uint32_t b0, b1, b2, b3;
                asm volatile("ldmatrix.sync.aligned.m8n8.x4.shared.b16 {%0,%1,%2,%3}, [%4];"
                             : "=r"(b0), "=r"(b1), "=r"(b2), "=r"(b3)
                             : "r"(smem + boff + p * (16 * WSROW * 2) + ks * 32));
                g_Wfrag[b * 2048 + (ks * 8 + p) * 32 + lane] = make_uint4(b0, b1, b2, b3);
            }
        }
    }
}

// -------------------- proj: C = A @ W ---------------------------------------
__global__ void __launch_bounds__(NT, 3)
proj_mm(const float* __restrict__ A, int widx, float* __restrict__ C, int M) {
    extern __shared__ char sm[];
    uint32_t smem = s2u(sm);
    int tid = threadIdx.x, wid = tid >> 5, lane = tid & 31;
    int gid = lane >> 2, tg = lane & 3;
    int m0 = blockIdx.x * TILE_M;

    char* wAhi = sm + SM_AHI + wid * 16 * (WSROW * 2);
    char* wAlo = sm + SM_ALO + wid * 16 * (WSROW * 2);
    stage_warpA(wAhi, wAlo, A, m0 + wid * 16, M, lane);
    __syncwarp();

    uint32_t aHi = smem + SM_AHI + (uint32_t)wid * 16 * (WSROW * 2) + a_lane_off(lane);
    uint32_t aLo = aHi + (SM_ALO - SM_AHI);

    float acc[16][4];
    zero_acc(acc);
    gemm2(aHi, aLo, g_Wfrag + widx * 2048 + lane, acc);

    int r0 = m0 + wid * 16 + gid, r1 = r0 + 8;
    #pragma unroll
    for (int nf = 0; nf < 16; nf++) {
        int col = nf * 8 + tg * 2;
        if (r0 < M) *reinterpret_cast<float2*>(C + (size_t)r0 * DD + col) = make_float2(acc[nf][0], acc[nf][1]);
        if (r1 < M) *reinterpret_cast<float2*>(C + (size_t)r1 * DD + col) = make_float2(acc[nf][2], acc[nf][3]);
    }
}

// -------------------- edge kernel (sync-free) --------------------------------
__global__ void __launch_bounds__(NT, 3)
edge_mm(const float* __restrict__ m2g, const int* __restrict__ src, const int* __restrict__ dst,
        const float* __restrict__ b0, const float* __restrict__ b1e,
        const float* __restrict__ ge, const float* __restrict__ be) {
    extern __shared__ char sm[];
    uint32_t smem = s2u(sm);
    int tid = threadIdx.x, wid = tid >> 5, lane = tid & 31;
    int gid = lane >> 2, tg = lane & 3;
    int e0 = blockIdx.x * TILE_M;

    char* wAhi = sm + SM_AHI + wid * 16 * (WSROW * 2);
    char* wAlo = sm + SM_ALO + wid * 16 * (WSROW * 2);
    stage_warpA(wAhi, wAlo, m2g, e0 + wid * 16, N_EDGE_C, lane);
    __syncwarp();

    uint32_t aHi = smem + SM_AHI + (uint32_t)wid * 16 * (WSROW * 2) + a_lane_off(lane);
    uint32_t aLo = aHi + (SM_ALO - SM_AHI);

    // pre-init acc with Pmesh[src] + Pgrid[dst] + b0 (long-latency LDGs up front)
    int r0l = wid * 16 + gid, r1l = r0l + 8;
    int er0 = e0 + r0l, er1 = e0 + r1l;
    int s0 = __ldg(src + er0), d0 = __ldg(dst + er0);
    int s1 = __ldg(src + er1), d1 = __ldg(dst + er1);

    float acc[16][4];
    #pragma unroll
    for (int nf = 0; nf < 16; nf++) {
        int col = nf * 8 + tg * 2;
        float2 bb = ld2(b0 + col);
        float2 pm0 = ld2(g_Pmesh + (size_t)s0 * DD + col);
        float2 pg0 = ld2(g_Pgrid + (size_t)d0 * DD + col);
        float2 pm1 = ld2(g_Pmesh + (size_t)s1 * DD + col);
        float2 pg1 = ld2(g_Pgrid + (size_t)d1 * DD + col);
        acc[nf][0] = bb.x + pm0.x + pg0.x;
        acc[nf][1] = bb.y + pm0.y + pg0.y;
        acc[nf][2] = bb.x + pm1.x + pg1.x;
        acc[nf][3] = bb.y + pm1.y + pg1.y;
    }

    gemm2(aHi, aLo, g_Wfrag + 2 * 2048 + lane, acc);     // += m2g @ We

    // silu -> h back into this warp's own A rows
    #pragma unroll
    for (int nf = 0; nf < 16; nf++) {
        int col = nf * 8 + tg * 2;
        conv_store2(wAhi, wAlo, gid,     col, silu_f(acc[nf][0]), silu_f(acc[nf][1]));
        conv_store2(wAhi, wAlo, gid + 8, col, silu_f(acc[nf][2]), silu_f(acc[nf][3]));
    }
    __syncwarp();

    zero_acc(acc);
    gemm2(aHi, aLo, g_Wfrag + 3 * 2048 + lane, acc);     // h @ W1e

    // +b1e, LayerNorm (warp owns full rows), store efeat
    float s1a = 0.f, s2a = 0.f, s1b = 0.f, s2b = 0.f;
    #pragma unroll
    for (int nf = 0; nf < 16; nf++) {
        int col = nf * 8 + tg * 2;
        float2 bb = ld2(b1e + col);
        acc[nf][0] += bb.x; acc[nf][1] += bb.y;
        acc[nf][2] += bb.x; acc[nf][3] += bb.y;
        s1a += acc[nf][0] + acc[nf][1];
        s2a += acc[nf][0]*acc[nf][0] + acc[nf][1]*acc[nf][1];
        s1b += acc[nf][2] + acc[nf][3];
        s2b += acc[nf][2]*acc[nf][2] + acc[nf][3]*acc[nf][3];
    }
    s1a = qsum(s1a); s2a = qsum(s2a); s1b = qsum(s1b); s2b = qsum(s2b);
    float mu0 = s1a * 0.0078125f, rstd0 = rsqrtf(s2a * 0.0078125f - mu0*mu0 + 1e-5f);
    float mu1 = s1b * 0.0078125f, rstd1 = rsqrtf(s2b * 0.0078125f - mu1*mu1 + 1e-5f);
    #pragma unroll
    for (int nf = 0; nf < 16; nf++) {
        int col = nf * 8 + tg * 2;
        float2 gv = ld2(ge + col), bv = ld2(be + col);
        *reinterpret_cast<float2*>(g_efeat + (size_t)er0 * DD + col) =
            make_float2((acc[nf][0]-mu0)*rstd0*gv.x + bv.x, (acc[nf][1]-mu0)*rstd0*gv.y + bv.y);
        *reinterpret_cast<float2*>(g_efeat + (size_t)er1 * DD + col) =
            make_float2((acc[nf][2]-mu1)*rstd1*gv.x + bv.x, (acc[nf][3]-mu1)*rstd1*gv.y + bv.y);
    }
}

// -------------------- node kernel (sync-free) --------------------------------
__global__ void __launch_bounds__(NT, 3)
node_mm(const float* __restrict__ grid, const int* __restrict__ dst,
        const float* __restrict__ bn0, const float* __restrict__ bn1,
        const float* __restrict__ gn, const float* __restrict__ bnv,
        float* __restrict__ out) {
    extern __shared__ char sm[];
    uint32_t smem = s2u(sm);
    int tid = threadIdx.x, wid = tid >> 5, lane = tid & 31;
    int gid = lane >> 2, tg = lane & 3;
    int n0 = blockIdx.x * TILE_M;

    // per-row edge ranges in lane registers (dst sorted); lane<16 owns row 16w+lane
    int myLo = 0, myHi = 0;
    if (lane < 16) {
        int n = n0 + wid * 16 + lane;
        int lo = 0, hi = N_EDGE_C;
        while (lo < hi) { int m = (lo + hi) >> 1; if (__ldg(dst + m) <  n) lo = m + 1; else hi = m; }
        myLo = lo;
        int lo2 = lo, hi2 = N_EDGE_C;
        while (lo2 < hi2) { int m = (lo2 + hi2) >> 1; if (__ldg(dst + m) <= n) lo2 = m + 1; else hi2 = m; }
        myHi = lo2;
    }

    char* wAhi = sm + SM_AHI + wid * 16 * (WSROW * 2);
    char* wAlo = sm + SM_ALO + wid * 16 * (WSROW * 2);
    uint32_t aHi = smem + SM_AHI + (uint32_t)wid * 16 * (WSROW * 2) + a_lane_off(lane);
    uint32_t aLo = aHi + (SM_ALO - SM_AHI);

    // pass 1: grid tile @ Wn0[0:128)
    stage_warpA(wAhi, wAlo, grid, n0 + wid * 16, N_GRID_C, lane);
    __syncwarp();
    float acc[16][4];
    zero_acc(acc);
    gemm2(aHi, aLo, g_Wfrag + 4 * 2048 + lane, acc);

    // pass 2: segment-sum into own A rows, then @ Wn0[128:256)
    {
        int c4 = lane * 4;
        #pragma unroll 1
        for (int i = 0; i < 16; i++) {
            int lo = __shfl_sync(0xffffffffu, myLo, i);
            int hi = __shfl_sync(0xffffffffu, myHi, i);
            float4 s = make_float4(0.f, 0.f, 0.f, 0.f);
            for (int e = lo; e < hi; e++) {
                float4 v = ld4(g_efeat + (size_t)e * DD + c4);
                s.x += v.x; s.y += v.y; s.z += v.z; s.w += v.w;
            }
            conv_store2(wAhi, wAlo, i, c4,     s.x, s.y);
            conv_store2(wAhi, wAlo, i, c4 + 2, s.z, s.w);
        }
    }
    __syncwarp();
    gemm2(aHi, aLo, g_Wfrag + 5 * 2048 + lane, acc);     // accumulate

    // silu(+bn0) -> h into own A rows
    #pragma unroll
    for (int nf = 0; nf < 16; nf++) {
        int col = nf * 8 + tg * 2;
        float2 bb = ld2(bn0 + col);
        conv_store2(wAhi, wAlo, gid,     col, silu_f(acc[nf][0] + bb.x), silu_f(acc[nf][1] + bb.y));
        conv_store2(wAhi, wAlo, gid + 8, col, silu_f(acc[nf][2] + bb.x), silu_f(acc[nf][3] + bb.y));
    }
    __syncwarp();

    zero_acc(acc);
    gemm2(aHi, aLo, g_Wfrag + 6 * 2048 + lane, acc);     // h @ Wn1

    // +bn1, LayerNorm, +grid residual, store
    int r0 = n0 + wid * 16 + gid, r1 = r0 + 8;
    float s1a = 0.f, s2a = 0.f, s1b = 0.f, s2b = 0.f;
    #pragma unroll
    for (int nf = 0; nf < 16; nf++) {
        int col = nf * 8 + tg * 2;
        float2 bb = ld2(bn1 + col);
        acc[nf][0] += bb.x; acc[nf][1] += bb.y;
        acc[nf][2] += bb.x; acc[nf][3] += bb.y;
        s1a += acc[nf][0] + acc[nf][1];
        s2a += acc[nf][0]*acc[nf][0] + acc[nf][1]*acc[nf][1];
        s1b += acc[nf][2] + acc[nf][3];
        s2b += acc[nf][2]*acc[nf][2] + acc[nf][3]*acc[nf][3];
    }
    s1a = qsum(s1a); s2a = qsum(s2a); s1b = qsum(s1b); s2b = qsum(s2b);
    float mu0 = s1a * 0.0078125f, rstd0 = rsqrtf(s2a * 0.0078125f - mu0*mu0 + 1e-5f);
    float mu1 = s1b * 0.0078125f, rstd1 = rsqrtf(s2b * 0.0078125f - mu1*mu1 + 1e-5f);
    #pragma unroll
    for (int nf = 0; nf < 16; nf++) {
        int col = nf * 8 + tg * 2;
        float2 gv = ld2(gn + col), bv = ld2(bnv + col);
        float2 gr0 = ld2(grid + (size_t)r0 * DD + col);
        float2 gr1 = ld2(grid + (size_t)r1 * DD + col);
        *reinterpret_cast<float2*>(out + (size_t)r0 * DD + col) =
            make_float2((acc[nf][0]-mu0)*rstd0*gv.x + bv.x + gr0.x,
                        (acc[nf][1]-mu0)*rstd0*gv.y + bv.y + gr0.y);
        *reinterpret_cast<float2*>(out + (size_t)r1 * DD + col) =
            make_float2((acc[nf][2]-mu1)*rstd1*gv.x + bv.x + gr1.x,
                        (acc[nf][3]-mu1)*rstd1*gv.y + bv.y + gr1.y);
    }
}

// -------------------- launch -------------------------------------------------
extern "C" void kernel_launch(void* const* d_in, const int* in_sizes, int n_in,
                              void* d_out, int out_size) {
    (void)in_sizes; (void)n_in; (void)out_size;

    const float* m2g  = (const float*)d_in[0];
    const float* grid = (const float*)d_in[1];
    const float* mesh = (const float*)d_in[2];
    const int*   src  = (const int*)  d_in[3];
    const int*   dst  = (const int*)  d_in[4];
    const float* We   = (const float*)d_in[5];
    const float* Ws   = (const float*)d_in[6];
    const float* Wd   = (const float*)d_in[7];
    const float* b0   = (const float*)d_in[8];
    const float* W1e  = (const float*)d_in[9];
    const float* b1e  = (const float*)d_in[10];
    const float* ge   = (const float*)d_in[11];
    const float* be   = (const float*)d_in[12];
    const float* Wn0  = (const float*)d_in[13];
    const float* bn0  = (const float*)d_in[14];
    const float* Wn1  = (const float*)d_in[15];
    const float* bn1  = (const float*)d_in[16];
    const float* gn   = (const float*)d_in[17];
    const float* bn   = (const float*)d_in[18];
    float* out = (float*)d_out;

    const int CONVW_SMEM = DD * WSROW * 2;  // 34816
    cudaFuncSetAttribute(convw_kernel, cudaFuncAttributeMaxDynamicSharedMemorySize, CONVW_SMEM);
    cudaFuncSetAttribute(proj_mm, cudaFuncAttributeMaxDynamicSharedMemorySize, SM_TOTAL);
    cudaFuncSetAttribute(edge_mm, cudaFuncAttributeMaxDynamicSharedMemorySize, SM_TOTAL);
    cudaFuncSetAttribute(node_mm, cudaFuncAttributeMaxDynamicSharedMemorySize, SM_TOTAL);

    void *pm = nullptr, *pg = nullptr;
    cudaGetSymbolAddress(&pm, g_Pmesh);
    cudaGetSymbolAddress(&pg, g_Pgrid);

    convw_kernel<<<7, 256, CONVW_SMEM>>>(Ws, Wd, We, W1e, Wn0, Wn1);

    int gb_mesh = (N_MESH_C + TILE_M - 1) / TILE_M;
    int gb_grid = (N_GRID_C + TILE_M - 1) / TILE_M;
    int gb_edge = (N_EDGE_C + TILE_M - 1) / TILE_M;

    proj_mm<<<gb_mesh, NT, SM_TOTAL>>>(mesh, 0, (float*)pm, N_MESH_C);
    proj_mm<<<gb_grid, NT, SM_TOTAL>>>(grid, 1, (float*)pg, N_GRID_C);
    edge_mm<<<gb_edge, NT, SM_TOTAL>>>(m2g, src, dst, b0, b1e, ge, be);
    node_mm<<<gb_grid, NT, SM_TOTAL>>>(grid, dst, bn0, bn1, gn, bn, out);
}